// round 2
// baseline (speedup 1.0000x reference)
#include <cuda_runtime.h>
#include <math.h>

#define LNUM 4
#define DM   256
#define NH   8
#define DHH  32
#define DI   1024
#define SEG  1024
#define MEML 1024
#define KL   2048
#define BSZ  2
#define NLD  12
#define H3   768          // 3*H*DH
#define PRED_N (BSZ*NLD*SEG)
#define SCALE 0.17677669529663687f   // 1/sqrt(32)

// ---------------- scratch (static device globals; no runtime allocation) ----------------
__device__ float g_core [SEG*BSZ*DM];
__device__ float g_cat  [KL*BSZ*DM];
__device__ float g_heads[KL*BSZ*H3];
__device__ float g_r    [KL*DM];
__device__ float g_rk   [KL*DM];
__device__ float g_vec  [SEG*BSZ*DM];
__device__ float g_mid  [SEG*BSZ*DI];
__device__ float g_AC   [(size_t)BSZ*NH*SEG*KL];   // scores / probs (in-place)
__device__ float g_BD   [(size_t)BSZ*NH*SEG*KL];   // pre-shift BD

__device__ __forceinline__ float* bufsel(int id) {
    switch (id) {
        case 0: return g_cat;
        case 1: return g_r;
        case 2: return g_vec;
        case 3: return g_core;
        case 4: return g_mid;
        case 5: return g_heads;
        case 6: return g_rk;
    }
    return g_core;
}

// ---------------- input projection: core = src^T @ W_in + b_in ; also mems_out[0] ----------------
__global__ void k_input_proj(const float* __restrict__ src, const float* __restrict__ W_in,
                             const float* __restrict__ b_in, float* __restrict__ memout) {
    int idx = blockIdx.x * blockDim.x + threadIdx.x;
    if (idx >= SEG*BSZ*DM) return;
    int d  = idx & (DM - 1);
    int sb = idx >> 8;       // DM = 256
    int b  = sb & 1;
    int s  = sb >> 1;
    float acc = b_in[d];
#pragma unroll
    for (int l = 0; l < NLD; l++)
        acc += src[((size_t)b * NLD + l) * SEG + s] * W_in[l * DM + d];
    g_core[idx] = acc;
    memout[idx] = acc;   // new_mems[0] == hids[0]
}

// ---------------- positional embedding r[KLEN, D] ----------------
__global__ void k_pos() {
    int idx = blockIdx.x * blockDim.x + threadIdx.x;
    if (idx >= KL * DM) return;
    int d = idx & (DM - 1);
    int j = idx >> 8;
    float pos = (float)(KL - 1 - j);
    int f = (d < 128) ? d : d - 128;
    float inv = powf(10000.f, -(float)f / 128.f);
    float v = pos * inv;
    g_r[idx] = (d < 128) ? sinf(v) : cosf(v);
}

// ---------------- cat = [mems_i ; core] ----------------
__global__ void k_cat(const float* __restrict__ mems_i) {
    int idx = blockIdx.x * blockDim.x + threadIdx.x;
    if (idx >= KL*BSZ*DM) return;
    g_cat[idx] = (idx < MEML*BSZ*DM) ? mems_i[idx] : g_core[idx - MEML*BSZ*DM];
}

// ---------------- generic SGEMM: C[M,N] = A[M,K] @ B[K,N] (+bias)(+relu) ----------------
// 64x64 tile, BK=16, 256 threads, 4x4 per thread. M,N multiples of 64; K multiple of 16.
__global__ void k_sgemm(int aid, const float* __restrict__ Bw, int cid,
                        int M, int N, int K,
                        const float* __restrict__ bias, int relu) {
    const float* A = bufsel(aid);
    float* C = bufsel(cid);
    __shared__ float As[64][16];
    __shared__ float Bs[16][64];
    int t  = threadIdx.x;
    int tx = t & 15, ty = t >> 4;
    int m0 = blockIdx.y * 64, n0 = blockIdx.x * 64;
    float acc[4][4] = {};
    int ar = t >> 2, ac4 = (t & 3) * 4;
    int br = t >> 4, bc4 = (t & 15) * 4;
    for (int k0 = 0; k0 < K; k0 += 16) {
        float4 va = *(const float4*)(A  + (size_t)(m0 + ar) * K + k0 + ac4);
        *(float4*)(&As[ar][ac4]) = va;
        float4 vb = *(const float4*)(Bw + (size_t)(k0 + br) * N + n0 + bc4);
        *(float4*)(&Bs[br][bc4]) = vb;
        __syncthreads();
#pragma unroll
        for (int kk = 0; kk < 16; kk++) {
            float av[4];
#pragma unroll
            for (int i = 0; i < 4; i++) av[i] = As[ty*4+i][kk];
            float4 b4 = *(const float4*)(&Bs[kk][tx*4]);
            float bv[4] = {b4.x, b4.y, b4.z, b4.w};
#pragma unroll
            for (int i = 0; i < 4; i++)
#pragma unroll
                for (int j = 0; j < 4; j++)
                    acc[i][j] += av[i] * bv[j];
        }
        __syncthreads();
    }
    float bb[4] = {0.f, 0.f, 0.f, 0.f};
    if (bias) {
#pragma unroll
        for (int j = 0; j < 4; j++) bb[j] = bias[n0 + tx*4 + j];
    }
#pragma unroll
    for (int i = 0; i < 4; i++) {
        float4 o;
        o.x = acc[i][0] + bb[0]; o.y = acc[i][1] + bb[1];
        o.z = acc[i][2] + bb[2]; o.w = acc[i][3] + bb[3];
        if (relu) {
            o.x = fmaxf(o.x, 0.f); o.y = fmaxf(o.y, 0.f);
            o.z = fmaxf(o.z, 0.f); o.w = fmaxf(o.w, 0.f);
        }
        *(float4*)(C + (size_t)(m0 + ty*4 + i) * N + n0 + tx*4) = o;
    }
}

// ---------------- QK^T kernel: mode 0 -> AC (K from heads), mode 1 -> BDpre (K from rk) ----------------
// per (b,h): C[i,j] = sum_d (Q[i,d]+qbias[d]) * Kmat[j,d] ; DH=32 fully resident.
__global__ void k_qk(int mode, const float* __restrict__ qbias) {
    int bh = blockIdx.z, b = bh >> 3, h = bh & 7;
    int i0 = blockIdx.y * 64, j0 = blockIdx.x * 64;
    const float* Qp = g_heads + (size_t)(MEML*BSZ + b) * H3 + h*DHH;
    const float* Kp; int kstr;
    float* Cp;
    if (mode == 0) { Kp = g_heads + (size_t)b*H3 + DM + h*DHH; kstr = BSZ*H3; Cp = g_AC; }
    else           { Kp = g_rk + h*DHH;                        kstr = DM;     Cp = g_BD; }
    Cp += (size_t)bh * SEG * KL;
    const float* qb = qbias + h*DHH;
    __shared__ float Qs[64][33];
    __shared__ float Ks[64][33];
    int t = threadIdx.x;
    for (int l = t; l < 512; l += 256) {
        int r = l >> 3, c = (l & 7) * 4;
        float4 vq = *(const float4*)(Qp + (size_t)(i0 + r) * (BSZ*H3) + c);
        Qs[r][c]   = vq.x + qb[c];   Qs[r][c+1] = vq.y + qb[c+1];
        Qs[r][c+2] = vq.z + qb[c+2]; Qs[r][c+3] = vq.w + qb[c+3];
        float4 vk = *(const float4*)(Kp + (size_t)(j0 + r) * kstr + c);
        Ks[r][c]   = vk.x; Ks[r][c+1] = vk.y;
        Ks[r][c+2] = vk.z; Ks[r][c+3] = vk.w;
    }
    __syncthreads();
    int tx = t & 15, ty = t >> 4;
    float acc[4][4] = {};
#pragma unroll
    for (int d = 0; d < DHH; d++) {
        float qv[4], kv[4];
#pragma unroll
        for (int i = 0; i < 4; i++) qv[i] = Qs[ty*4+i][d];
#pragma unroll
        for (int j = 0; j < 4; j++) kv[j] = Ks[tx*4+j][d];
#pragma unroll
        for (int i = 0; i < 4; i++)
#pragma unroll
            for (int j = 0; j < 4; j++)
                acc[i][j] += qv[i] * kv[j];
    }
#pragma unroll
    for (int i = 0; i < 4; i++) {
        float4 o = {acc[i][0], acc[i][1], acc[i][2], acc[i][3]};
        *(float4*)(Cp + (size_t)(i0 + ty*4 + i) * KL + j0 + tx*4) = o;
    }
}

// ---------------- fused rel_shift + combine + mask + softmax; prob written in-place over AC ----------------
__global__ void k_softmax(const unsigned char* __restrict__ mask) {
    int i = blockIdx.x, bh = blockIdx.y;
    int t = threadIdx.x;
    size_t rowoff = ((size_t)bh * SEG + i) * KL;
    float* ac = g_AC + rowoff;
    float vals[8];
    float mx = -INFINITY;
#pragma unroll
    for (int r2 = 0; r2 < 8; r2++) {
        int j = t + r2 * 256;
        int f = SEG + i * KL + j;              // rel_shift flat index
        int a = f / (KL + 1);
        int p = f - a * (KL + 1);
        float bd = (p == 0) ? 0.f : g_BD[((size_t)bh * SEG + a) * KL + (p - 1)];
        float s = (ac[j] + bd) * SCALE;
        if (mask[(size_t)i * KL + j]) s = -INFINITY;
        vals[r2] = s;
        mx = fmaxf(mx, s);
    }
    __shared__ float red[256];
    red[t] = mx; __syncthreads();
    for (int s2 = 128; s2 > 0; s2 >>= 1) { if (t < s2) red[t] = fmaxf(red[t], red[t+s2]); __syncthreads(); }
    float rowmax = red[0]; __syncthreads();
    float sum = 0.f;
#pragma unroll
    for (int r2 = 0; r2 < 8; r2++) { vals[r2] = expf(vals[r2] - rowmax); sum += vals[r2]; }
    red[t] = sum; __syncthreads();
    for (int s2 = 128; s2 > 0; s2 >>= 1) { if (t < s2) red[t] += red[t+s2]; __syncthreads(); }
    float inv = 1.f / red[0];
#pragma unroll
    for (int r2 = 0; r2 < 8; r2++) ac[t + r2*256] = vals[r2] * inv;
}

// ---------------- PV: per (b,h): vec[i, h*32+d] = sum_j prob[i,j] * V[j,d] ----------------
__global__ void k_pv() {
    int bh = blockIdx.y, b = bh >> 3, h = bh & 7;
    int i0 = blockIdx.x * 64;
    const float* P = g_AC + (size_t)bh * SEG * KL;
    const float* V = g_heads + (size_t)b * H3 + 2*DM + h*DHH;
    __shared__ float Ps[64][36];
    __shared__ float Vs[32][33];
    int t = threadIdx.x;
    int d = t & 31, iy = t >> 5;
    float acc[8] = {0,0,0,0,0,0,0,0};
    for (int j0 = 0; j0 < KL; j0 += 32) {
        for (int l = t; l < 512; l += 256) {
            int r = l >> 3, c = (l & 7) * 4;
            float4 v = *(const float4*)(P + (size_t)(i0 + r) * KL + j0 + c);
            Ps[r][c] = v.x; Ps[r][c+1] = v.y; Ps[r][c+2] = v.z; Ps[r][c+3] = v.w;
        }
        {
            int r = t >> 3, c = (t & 7) * 4;
            float4 v = *(const float4*)(V + (size_t)(j0 + r) * (BSZ*H3) + c);
            Vs[r][c] = v.x; Vs[r][c+1] = v.y; Vs[r][c+2] = v.z; Vs[r][c+3] = v.w;
        }
        __syncthreads();
#pragma unroll
        for (int jj = 0; jj < 32; jj += 4) {
            float v0 = Vs[jj][d], v1 = Vs[jj+1][d], v2 = Vs[jj+2][d], v3 = Vs[jj+3][d];
#pragma unroll
            for (int r2 = 0; r2 < 8; r2++) {
                float4 p4 = *(const float4*)(&Ps[iy + r2*8][jj]);
                acc[r2] += p4.x*v0 + p4.y*v1 + p4.z*v2 + p4.w*v3;
            }
        }
        __syncthreads();
    }
#pragma unroll
    for (int r2 = 0; r2 < 8; r2++)
        g_vec[(size_t)((i0 + iy + r2*8) * BSZ + b) * DM + h*DHH + d] = acc[r2];
}

// ---------------- residual add + LayerNorm; optional write to mems output ----------------
__global__ void k_addln(int did, const float* __restrict__ gamma, const float* __restrict__ beta,
                        float* __restrict__ memout) {
    const float* delta = bufsel(did);
    int row = blockIdx.x, d = threadIdx.x;
    size_t off = (size_t)row * DM + d;
    float x = g_core[off] + delta[off];
    __shared__ float red[DM];
    red[d] = x; __syncthreads();
    for (int s = 128; s > 0; s >>= 1) { if (d < s) red[d] += red[d+s]; __syncthreads(); }
    float mu = red[0] * (1.f/DM); __syncthreads();
    float c = x - mu;
    red[d] = c * c; __syncthreads();
    for (int s = 128; s > 0; s >>= 1) { if (d < s) red[d] += red[d+s]; __syncthreads(); }
    float var = red[0] * (1.f/DM);
    float y = c * (1.f / sqrtf(var + 1e-5f)) * gamma[d] + beta[d];
    g_core[off] = y;
    if (memout) memout[off] = y;
}

// ---------------- decoder: pred[b,l,s] = core[s,b,:] . W_dec[:,l] + b_dec[l] ----------------
__global__ void k_dec(const float* __restrict__ Wd, const float* __restrict__ bd,
                      float* __restrict__ pred) {
    int idx = blockIdx.x * blockDim.x + threadIdx.x;
    if (idx >= PRED_N) return;
    int s = idx % SEG;
    int l = (idx / SEG) % NLD;
    int b = idx / (SEG * NLD);
    const float* crow = g_core + (size_t)(s * BSZ + b) * DM;
    float acc = bd[l];
    for (int d2 = 0; d2 < DM; d2++) acc += crow[d2] * Wd[d2 * NLD + l];
    pred[idx] = acc;
}

// ---------------- host launcher ----------------
extern "C" void kernel_launch(void* const* d_in, const int* in_sizes, int n_in,
                              void* d_out, int out_size) {
    (void)in_sizes; (void)n_in; (void)out_size;
    const float* src      = (const float*)d_in[0];
    const float* mems     = (const float*)d_in[1];
    const unsigned char* mask = (const unsigned char*)d_in[2];
    const float* W_in     = (const float*)d_in[3];
    const float* b_in     = (const float*)d_in[4];
    const float* qkv_w    = (const float*)d_in[5];
    const float* r_net_w  = (const float*)d_in[6];
    const float* o_w      = (const float*)d_in[7];
    const float* ln1_g    = (const float*)d_in[8];
    const float* ln1_b    = (const float*)d_in[9];
    const float* ff_w1    = (const float*)d_in[10];
    const float* ff_b1    = (const float*)d_in[11];
    const float* ff_w2    = (const float*)d_in[12];
    const float* ff_b2    = (const float*)d_in[13];
    const float* ln2_g    = (const float*)d_in[14];
    const float* ln2_b    = (const float*)d_in[15];
    const float* W_dec    = (const float*)d_in[16];
    const float* b_dec    = (const float*)d_in[17];
    const float* r_w_bias = (const float*)d_in[18];
    const float* r_r_bias = (const float*)d_in[19];

    float* out    = (float*)d_out;
    float* pred   = out;
    float* memout = out + PRED_N;

    k_input_proj<<<(SEG*BSZ*DM + 255)/256, 256>>>(src, W_in, b_in, memout);
    k_pos<<<(KL*DM + 255)/256, 256>>>();

    for (int i = 0; i < LNUM; i++) {
        k_cat<<<(KL*BSZ*DM + 255)/256, 256>>>(mems + (size_t)i * MEML*BSZ*DM);
        // heads = cat @ qkv_w[i]   [4096 x 768 x 256]
        k_sgemm<<<dim3(H3/64, (KL*BSZ)/64), 256>>>(0, qkv_w + (size_t)i*DM*H3, 5,
                                                   KL*BSZ, H3, DM, nullptr, 0);
        // rk = r @ r_net_w[i]      [2048 x 256 x 256]
        k_sgemm<<<dim3(DM/64, KL/64), 256>>>(1, r_net_w + (size_t)i*DM*DM, 6,
                                             KL, DM, DM, nullptr, 0);
        k_qk<<<dim3(KL/64, SEG/64, BSZ*NH), 256>>>(0, r_w_bias);
        k_qk<<<dim3(KL/64, SEG/64, BSZ*NH), 256>>>(1, r_r_bias);
        k_softmax<<<dim3(SEG, BSZ*NH), 256>>>(mask);
        k_pv<<<dim3(SEG/64, BSZ*NH), 256>>>();
        // attn output projection     [2048 x 256 x 256]
        k_sgemm<<<dim3(DM/64, (SEG*BSZ)/64), 256>>>(2, o_w + (size_t)i*DM*DM, 4,
                                                    SEG*BSZ, DM, DM, nullptr, 0);
        k_addln<<<SEG*BSZ, DM>>>(4, ln1_g + i*DM, ln1_b + i*DM, nullptr);
        // ff1 + bias + relu          [2048 x 1024 x 256]
        k_sgemm<<<dim3(DI/64, (SEG*BSZ)/64), 256>>>(3, ff_w1 + (size_t)i*DM*DI, 4,
                                                    SEG*BSZ, DI, DM, ff_b1 + i*DI, 1);
        // ff2 + bias                 [2048 x 256 x 1024]
        k_sgemm<<<dim3(DM/64, (SEG*BSZ)/64), 256>>>(4, ff_w2 + (size_t)i*DI*DM, 2,
                                                    SEG*BSZ, DM, DI, ff_b2 + i*DM, 0);
        k_addln<<<SEG*BSZ, DM>>>(2, ln2_g + i*DM, ln2_b + i*DM,
                                 memout + (size_t)(i+1)*SEG*BSZ*DM);
    }
    k_dec<<<(PRED_N + 255)/256, 256>>>(W_dec, b_dec, pred);
}

// round 3
// speedup vs baseline: 1.5113x; 1.5113x over previous
#include <cuda_runtime.h>
#include <math.h>

#define LNUM 4
#define DM   256
#define NH   8
#define DHH  32
#define DI   1024
#define SEG  1024
#define MEML 1024
#define KL   2048
#define BSZ  2
#define NLD  12
#define H3   768          // 3*H*DH
#define PRED_N (BSZ*NLD*SEG)
#define SCALE 0.17677669529663687f   // 1/sqrt(32)

// ---------------- scratch (static device globals; no runtime allocation) ----------------
__device__ float g_core [SEG*BSZ*DM];
__device__ float g_cat  [KL*BSZ*DM];
__device__ float g_heads[KL*BSZ*H3];
__device__ float g_r    [KL*DM];
__device__ float g_rk   [KL*DM];
__device__ float g_vec  [SEG*BSZ*DM];
__device__ float g_mid  [SEG*BSZ*DI];
__device__ float g_AC   [(size_t)BSZ*NH*SEG*KL];   // scores / probs (in-place)
__device__ float g_BD   [(size_t)BSZ*NH*SEG*KL];   // pre-shift BD

__device__ __forceinline__ float* bufsel(int id) {
    switch (id) {
        case 0: return g_cat;
        case 1: return g_r;
        case 2: return g_vec;
        case 3: return g_core;
        case 4: return g_mid;
        case 5: return g_heads;
        case 6: return g_rk;
    }
    return g_core;
}

// ---------------- tf32 helpers ----------------
__device__ __forceinline__ unsigned f2tf(float x) {
    unsigned u;
    asm("cvt.rna.tf32.f32 %0, %1;" : "=r"(u) : "f"(x));
    return u;
}
__device__ __forceinline__ void mma_tf32(float& c0, float& c1, float& c2, float& c3,
                                         unsigned a0, unsigned a1, unsigned a2, unsigned a3,
                                         unsigned b0, unsigned b1) {
    asm volatile(
        "mma.sync.aligned.m16n8k8.row.col.f32.tf32.tf32.f32 "
        "{%0,%1,%2,%3},{%4,%5,%6,%7},{%8,%9},{%0,%1,%2,%3};\n"
        : "+f"(c0), "+f"(c1), "+f"(c2), "+f"(c3)
        : "r"(a0), "r"(a1), "r"(a2), "r"(a3), "r"(b0), "r"(b1));
}

// ---------------- input projection: core = src^T @ W_in + b_in ; also mems_out[0] ----------------
__global__ void k_input_proj(const float* __restrict__ src, const float* __restrict__ W_in,
                             const float* __restrict__ b_in, float* __restrict__ memout) {
    int idx = blockIdx.x * blockDim.x + threadIdx.x;
    if (idx >= SEG*BSZ*DM) return;
    int d  = idx & (DM - 1);
    int sb = idx >> 8;
    int b  = sb & 1;
    int s  = sb >> 1;
    float acc = b_in[d];
#pragma unroll
    for (int l = 0; l < NLD; l++)
        acc += src[((size_t)b * NLD + l) * SEG + s] * W_in[l * DM + d];
    g_core[idx] = acc;
    memout[idx] = acc;   // new_mems[0] == hids[0]
}

// ---------------- positional embedding r[KLEN, D] ----------------
__global__ void k_pos() {
    int idx = blockIdx.x * blockDim.x + threadIdx.x;
    if (idx >= KL * DM) return;
    int d = idx & (DM - 1);
    int j = idx >> 8;
    float pos = (float)(KL - 1 - j);
    int f = (d < 128) ? d : d - 128;
    float inv = powf(10000.f, -(float)f / 128.f);
    float v = pos * inv;
    g_r[idx] = (d < 128) ? sinf(v) : cosf(v);
}

// ---------------- cat = [mems_i ; core] ----------------
__global__ void k_cat(const float* __restrict__ mems_i) {
    int idx = blockIdx.x * blockDim.x + threadIdx.x;
    if (idx >= KL*BSZ*DM) return;
    g_cat[idx] = (idx < MEML*BSZ*DM) ? mems_i[idx] : g_core[idx - MEML*BSZ*DM];
}

// ---------------- tf32 GEMM: C[M,N] = A[M,K] @ B[K,N] (+bias)(+relu) ----------------
// BM=128, BN=64, BK=16, 256 threads (8 warps: 4(M) x 2(N), warp tile 32x32).
__global__ void k_gemm_tf32(int aid, const float* __restrict__ Bw, int cid,
                            int M, int N, int K,
                            const float* __restrict__ bias, int relu) {
    const float* A = bufsel(aid);
    float* C = bufsel(cid);
    __shared__ unsigned As[128][20];   // stride 20 -> conflict-free quad access
    __shared__ unsigned Bs[16][72];    // stride 72 -> conflict-free quad access
    int t = threadIdx.x;
    int m0 = blockIdx.y * 128, n0 = blockIdx.x * 64;
    int lane = t & 31, g = lane >> 2, tg = lane & 3;
    int w = t >> 5;
    int wm = (w >> 1) * 32, wn = (w & 1) * 32;
    float c[2][4][4];
#pragma unroll
    for (int i = 0; i < 2; i++)
#pragma unroll
        for (int j = 0; j < 4; j++)
#pragma unroll
            for (int q = 0; q < 4; q++) c[i][j][q] = 0.f;

    for (int k0 = 0; k0 < K; k0 += 16) {
#pragma unroll
        for (int i = 0; i < 2; i++) {
            int f = t + i * 256;
            int r = f >> 2, c4 = (f & 3) * 4;
            float4 v = *(const float4*)(A + (size_t)(m0 + r) * K + k0 + c4);
            As[r][c4]   = f2tf(v.x); As[r][c4+1] = f2tf(v.y);
            As[r][c4+2] = f2tf(v.z); As[r][c4+3] = f2tf(v.w);
        }
        {
            int br = t >> 4, bc4 = (t & 15) * 4;
            float4 v = *(const float4*)(Bw + (size_t)(k0 + br) * N + n0 + bc4);
            Bs[br][bc4]   = f2tf(v.x); Bs[br][bc4+1] = f2tf(v.y);
            Bs[br][bc4+2] = f2tf(v.z); Bs[br][bc4+3] = f2tf(v.w);
        }
        __syncthreads();
#pragma unroll
        for (int ks = 0; ks < 16; ks += 8) {
            unsigned a[2][4], bfrag[4][2];
#pragma unroll
            for (int mt = 0; mt < 2; mt++) {
                int r = wm + mt * 16 + g;
                a[mt][0] = As[r][ks + tg];
                a[mt][1] = As[r + 8][ks + tg];
                a[mt][2] = As[r][ks + tg + 4];
                a[mt][3] = As[r + 8][ks + tg + 4];
            }
#pragma unroll
            for (int nt = 0; nt < 4; nt++) {
                int col = wn + nt * 8 + g;
                bfrag[nt][0] = Bs[ks + tg][col];
                bfrag[nt][1] = Bs[ks + tg + 4][col];
            }
#pragma unroll
            for (int mt = 0; mt < 2; mt++)
#pragma unroll
                for (int nt = 0; nt < 4; nt++)
                    mma_tf32(c[mt][nt][0], c[mt][nt][1], c[mt][nt][2], c[mt][nt][3],
                             a[mt][0], a[mt][1], a[mt][2], a[mt][3],
                             bfrag[nt][0], bfrag[nt][1]);
        }
        __syncthreads();
    }
    // epilogue
#pragma unroll
    for (int mt = 0; mt < 2; mt++) {
#pragma unroll
        for (int nt = 0; nt < 4; nt++) {
            int row = m0 + wm + mt * 16 + g;
            int col = n0 + wn + nt * 8 + 2 * tg;
            float b0 = 0.f, b1 = 0.f;
            if (bias) { b0 = bias[col]; b1 = bias[col + 1]; }
            float v0 = c[mt][nt][0] + b0, v1 = c[mt][nt][1] + b1;
            float v2 = c[mt][nt][2] + b0, v3 = c[mt][nt][3] + b1;
            if (relu) {
                v0 = fmaxf(v0, 0.f); v1 = fmaxf(v1, 0.f);
                v2 = fmaxf(v2, 0.f); v3 = fmaxf(v3, 0.f);
            }
            *(float2*)(C + (size_t)row * N + col)       = make_float2(v0, v1);
            *(float2*)(C + (size_t)(row + 8) * N + col) = make_float2(v2, v3);
        }
    }
}

// ---------------- tf32 QK^T: mode 0 -> AC (K from heads), mode 1 -> BDpre (K from rk) ----------------
// per (b,h): C[i,j] = sum_d (Q[i,d]+qbias[d]) * Kmat[j,d] ; K=DH=32 single smem shot.
// BM=128, BN=64, 256 threads (8 warps: 4x2, warp tile 32x32).
__global__ void k_qk_tf32(int mode, const float* __restrict__ qbias) {
    int bh = blockIdx.z, b = bh >> 3, h = bh & 7;
    int i0 = blockIdx.y * 128, j0 = blockIdx.x * 64;
    const float* Qp = g_heads + (size_t)(MEML*BSZ + b) * H3 + h*DHH;
    const float* Kp; int kstr;
    float* Cp;
    if (mode == 0) { Kp = g_heads + (size_t)b*H3 + DM + h*DHH; kstr = BSZ*H3; Cp = g_AC; }
    else           { Kp = g_rk + h*DHH;                        kstr = DM;     Cp = g_BD; }
    Cp += (size_t)bh * SEG * KL;
    const float* qb = qbias + h*DHH;

    __shared__ unsigned Qs[128][36];
    __shared__ unsigned Ks[64][36];
    int t = threadIdx.x;
    int lane = t & 31, g = lane >> 2, tg = lane & 3;
    int w = t >> 5;
    int wm = (w >> 1) * 32, wn = (w & 1) * 32;

#pragma unroll
    for (int i = 0; i < 4; i++) {
        int f = t + i * 256;
        int r = f >> 3, c4 = (f & 7) * 4;
        float4 v = *(const float4*)(Qp + (size_t)(i0 + r) * (BSZ*H3) + c4);
        Qs[r][c4]   = f2tf(v.x + qb[c4]);   Qs[r][c4+1] = f2tf(v.y + qb[c4+1]);
        Qs[r][c4+2] = f2tf(v.z + qb[c4+2]); Qs[r][c4+3] = f2tf(v.w + qb[c4+3]);
    }
#pragma unroll
    for (int i = 0; i < 2; i++) {
        int f = t + i * 256;
        int r = f >> 3, c4 = (f & 7) * 4;
        float4 v = *(const float4*)(Kp + (size_t)(j0 + r) * kstr + c4);
        Ks[r][c4]   = f2tf(v.x); Ks[r][c4+1] = f2tf(v.y);
        Ks[r][c4+2] = f2tf(v.z); Ks[r][c4+3] = f2tf(v.w);
    }
    __syncthreads();

    float c[2][4][4];
#pragma unroll
    for (int i = 0; i < 2; i++)
#pragma unroll
        for (int j = 0; j < 4; j++)
#pragma unroll
            for (int q = 0; q < 4; q++) c[i][j][q] = 0.f;

#pragma unroll
    for (int ks = 0; ks < 32; ks += 8) {
        unsigned a[2][4], bfrag[4][2];
#pragma unroll
        for (int mt = 0; mt < 2; mt++) {
            int r = wm + mt * 16 + g;
            a[mt][0] = Qs[r][ks + tg];
            a[mt][1] = Qs[r + 8][ks + tg];
            a[mt][2] = Qs[r][ks + tg + 4];
            a[mt][3] = Qs[r + 8][ks + tg + 4];
        }
#pragma unroll
        for (int nt = 0; nt < 4; nt++) {
            int col = wn + nt * 8 + g;
            bfrag[nt][0] = Ks[col][ks + tg];
            bfrag[nt][1] = Ks[col][ks + tg + 4];
        }
#pragma unroll
        for (int mt = 0; mt < 2; mt++)
#pragma unroll
            for (int nt = 0; nt < 4; nt++)
                mma_tf32(c[mt][nt][0], c[mt][nt][1], c[mt][nt][2], c[mt][nt][3],
                         a[mt][0], a[mt][1], a[mt][2], a[mt][3],
                         bfrag[nt][0], bfrag[nt][1]);
    }
#pragma unroll
    for (int mt = 0; mt < 2; mt++)
#pragma unroll
        for (int nt = 0; nt < 4; nt++) {
            int row = i0 + wm + mt * 16 + g;
            int col = j0 + wn + nt * 8 + 2 * tg;
            *(float2*)(Cp + (size_t)row * KL + col)       = make_float2(c[mt][nt][0], c[mt][nt][1]);
            *(float2*)(Cp + (size_t)(row + 8) * KL + col) = make_float2(c[mt][nt][2], c[mt][nt][3]);
        }
}

// ---------------- fused rel_shift + combine + mask + softmax; prob written in-place over AC ----------------
__global__ void k_softmax(const unsigned char* __restrict__ mask) {
    int i = blockIdx.x, bh = blockIdx.y;
    int t = threadIdx.x;
    size_t rowoff = ((size_t)bh * SEG + i) * KL;
    float* ac = g_AC + rowoff;
    float vals[8];
    float mx = -INFINITY;
#pragma unroll
    for (int r2 = 0; r2 < 8; r2++) {
        int j = t + r2 * 256;
        int f = SEG + i * KL + j;              // rel_shift flat index
        int a = f / (KL + 1);
        int p = f - a * (KL + 1);
        float bd = (p == 0) ? 0.f : g_BD[((size_t)bh * SEG + a) * KL + (p - 1)];
        float s = (ac[j] + bd) * SCALE;
        if (mask[(size_t)i * KL + j]) s = -INFINITY;
        vals[r2] = s;
        mx = fmaxf(mx, s);
    }
    __shared__ float red[256];
    red[t] = mx; __syncthreads();
    for (int s2 = 128; s2 > 0; s2 >>= 1) { if (t < s2) red[t] = fmaxf(red[t], red[t+s2]); __syncthreads(); }
    float rowmax = red[0]; __syncthreads();
    float sum = 0.f;
#pragma unroll
    for (int r2 = 0; r2 < 8; r2++) { vals[r2] = expf(vals[r2] - rowmax); sum += vals[r2]; }
    red[t] = sum; __syncthreads();
    for (int s2 = 128; s2 > 0; s2 >>= 1) { if (t < s2) red[t] += red[t+s2]; __syncthreads(); }
    float inv = 1.f / red[0];
#pragma unroll
    for (int r2 = 0; r2 < 8; r2++) ac[t + r2*256] = vals[r2] * inv;
}

// ---------------- tf32 PV: per (b,h): vec[i, h*32+d] = sum_j prob[i,j] * V[j,d] ----------------
// BM=64, BN=32, BK=32, 128 threads (4 warps, each 16 rows).
__global__ void k_pv_tf32() {
    int bh = blockIdx.y, b = bh >> 3, h = bh & 7;
    int i0 = blockIdx.x * 64;
    const float* P = g_AC + (size_t)bh * SEG * KL;
    const float* V = g_heads + (size_t)b * H3 + 2*DM + h*DHH;
    const int sV = BSZ*H3;

    __shared__ unsigned Ps[64][36];
    __shared__ unsigned Vst[32][36];   // transposed: Vst[d][j_rel]
    int t = threadIdx.x;
    int lane = t & 31, g = lane >> 2, tg = lane & 3;
    int w = t >> 5;
    int wm = w * 16;

    float c[4][4];
#pragma unroll
    for (int j = 0; j < 4; j++)
#pragma unroll
        for (int q = 0; q < 4; q++) c[j][q] = 0.f;

    for (int j0 = 0; j0 < KL; j0 += 32) {
#pragma unroll
        for (int i = 0; i < 4; i++) {
            int f = t + i * 128;
            int r = f >> 3, c4 = (f & 7) * 4;
            float4 v = *(const float4*)(P + (size_t)(i0 + r) * KL + j0 + c4);
            Ps[r][c4]   = f2tf(v.x); Ps[r][c4+1] = f2tf(v.y);
            Ps[r][c4+2] = f2tf(v.z); Ps[r][c4+3] = f2tf(v.w);
        }
#pragma unroll
        for (int i = 0; i < 2; i++) {
            int f = t + i * 128;
            int jr = f >> 3, c4 = (f & 7) * 4;
            float4 v = *(const float4*)(V + (size_t)(j0 + jr) * sV + c4);
            Vst[c4][jr]   = f2tf(v.x); Vst[c4+1][jr] = f2tf(v.y);
            Vst[c4+2][jr] = f2tf(v.z); Vst[c4+3][jr] = f2tf(v.w);
        }
        __syncthreads();
#pragma unroll
        for (int ks = 0; ks < 32; ks += 8) {
            unsigned a0 = Ps[wm + g][ks + tg];
            unsigned a1 = Ps[wm + g + 8][ks + tg];
            unsigned a2 = Ps[wm + g][ks + tg + 4];
            unsigned a3 = Ps[wm + g + 8][ks + tg + 4];
#pragma unroll
            for (int nt = 0; nt < 4; nt++) {
                unsigned b0 = Vst[nt * 8 + g][ks + tg];
                unsigned b1 = Vst[nt * 8 + g][ks + tg + 4];
                mma_tf32(c[nt][0], c[nt][1], c[nt][2], c[nt][3], a0, a1, a2, a3, b0, b1);
            }
        }
        __syncthreads();
    }
#pragma unroll
    for (int nt = 0; nt < 4; nt++) {
        int row = i0 + wm + g;
        int col = h*DHH + nt * 8 + 2 * tg;
        *(float2*)(g_vec + (size_t)(row * BSZ + b) * DM + col)       = make_float2(c[nt][0], c[nt][1]);
        *(float2*)(g_vec + (size_t)((row + 8) * BSZ + b) * DM + col) = make_float2(c[nt][2], c[nt][3]);
    }
}

// ---------------- residual add + LayerNorm; optional write to mems output ----------------
__global__ void k_addln(int did, const float* __restrict__ gamma, const float* __restrict__ beta,
                        float* __restrict__ memout) {
    const float* delta = bufsel(did);
    int row = blockIdx.x, d = threadIdx.x;
    size_t off = (size_t)row * DM + d;
    float x = g_core[off] + delta[off];
    __shared__ float red[DM];
    red[d] = x; __syncthreads();
    for (int s = 128; s > 0; s >>= 1) { if (d < s) red[d] += red[d+s]; __syncthreads(); }
    float mu = red[0] * (1.f/DM); __syncthreads();
    float c = x - mu;
    red[d] = c * c; __syncthreads();
    for (int s = 128; s > 0; s >>= 1) { if (d < s) red[d] += red[d+s]; __syncthreads(); }
    float var = red[0] * (1.f/DM);
    float y = c * (1.f / sqrtf(var + 1e-5f)) * gamma[d] + beta[d];
    g_core[off] = y;
    if (memout) memout[off] = y;
}

// ---------------- decoder: pred[b,l,s] = core[s,b,:] . W_dec[:,l] + b_dec[l] ----------------
// warp per (s,b) row; W_dec cached in smem.
__global__ void k_dec(const float* __restrict__ Wd, const float* __restrict__ bd,
                      float* __restrict__ pred) {
    __shared__ float Wds[DM * NLD];
    int t = threadIdx.x;
    for (int i = t; i < DM * NLD; i += 256) Wds[i] = Wd[i];
    __syncthreads();
    int lane = t & 31, w = t >> 5;
    int row = blockIdx.x * 8 + w;          // row = s*BSZ + b
    int b = row & 1, s = row >> 1;
    const float* crow = g_core + (size_t)row * DM;
    float v[8];
#pragma unroll
    for (int i = 0; i < 8; i++) v[i] = crow[lane + i * 32];
#pragma unroll
    for (int l = 0; l < NLD; l++) {
        float acc = 0.f;
#pragma unroll
        for (int i = 0; i < 8; i++) acc += v[i] * Wds[(lane + i * 32) * NLD + l];
#pragma unroll
        for (int o = 16; o > 0; o >>= 1) acc += __shfl_down_sync(0xffffffffu, acc, o);
        if (lane == 0)
            pred[((size_t)b * NLD + l) * SEG + s] = acc + bd[l];
    }
}

// ---------------- host launcher ----------------
extern "C" void kernel_launch(void* const* d_in, const int* in_sizes, int n_in,
                              void* d_out, int out_size) {
    (void)in_sizes; (void)n_in; (void)out_size;
    const float* src      = (const float*)d_in[0];
    const float* mems     = (const float*)d_in[1];
    const unsigned char* mask = (const unsigned char*)d_in[2];
    const float* W_in     = (const float*)d_in[3];
    const float* b_in     = (const float*)d_in[4];
    const float* qkv_w    = (const float*)d_in[5];
    const float* r_net_w  = (const float*)d_in[6];
    const float* o_w      = (const float*)d_in[7];
    const float* ln1_g    = (const float*)d_in[8];
    const float* ln1_b    = (const float*)d_in[9];
    const float* ff_w1    = (const float*)d_in[10];
    const float* ff_b1    = (const float*)d_in[11];
    const float* ff_w2    = (const float*)d_in[12];
    const float* ff_b2    = (const float*)d_in[13];
    const float* ln2_g    = (const float*)d_in[14];
    const float* ln2_b    = (const float*)d_in[15];
    const float* W_dec    = (const float*)d_in[16];
    const float* b_dec    = (const float*)d_in[17];
    const float* r_w_bias = (const float*)d_in[18];
    const float* r_r_bias = (const float*)d_in[19];

    float* out    = (float*)d_out;
    float* pred   = out;
    float* memout = out + PRED_N;

    k_input_proj<<<(SEG*BSZ*DM + 255)/256, 256>>>(src, W_in, b_in, memout);
    k_pos<<<(KL*DM + 255)/256, 256>>>();

    for (int i = 0; i < LNUM; i++) {
        k_cat<<<(KL*BSZ*DM + 255)/256, 256>>>(mems + (size_t)i * MEML*BSZ*DM);
        // heads = cat @ qkv_w[i]   [4096 x 768 x 256]
        k_gemm_tf32<<<dim3(H3/64, (KL*BSZ)/128), 256>>>(0, qkv_w + (size_t)i*DM*H3, 5,
                                                        KL*BSZ, H3, DM, nullptr, 0);
        // rk = r @ r_net_w[i]      [2048 x 256 x 256]
        k_gemm_tf32<<<dim3(DM/64, KL/128), 256>>>(1, r_net_w + (size_t)i*DM*DM, 6,
                                                  KL, DM, DM, nullptr, 0);
        k_qk_tf32<<<dim3(KL/64, SEG/128, BSZ*NH), 256>>>(0, r_w_bias);
        k_qk_tf32<<<dim3(KL/64, SEG/128, BSZ*NH), 256>>>(1, r_r_bias);
        k_softmax<<<dim3(SEG, BSZ*NH), 256>>>(mask);
        k_pv_tf32<<<dim3(SEG/64, BSZ*NH), 128>>>();
        // attn output projection     [2048 x 256 x 256]
        k_gemm_tf32<<<dim3(DM/64, (SEG*BSZ)/128), 256>>>(2, o_w + (size_t)i*DM*DM, 4,
                                                         SEG*BSZ, DM, DM, nullptr, 0);
        k_addln<<<SEG*BSZ, DM>>>(4, ln1_g + i*DM, ln1_b + i*DM, nullptr);
        // ff1 + bias + relu          [2048 x 1024 x 256]
        k_gemm_tf32<<<dim3(DI/64, (SEG*BSZ)/128), 256>>>(3, ff_w1 + (size_t)i*DM*DI, 4,
                                                         SEG*BSZ, DI, DM, ff_b1 + i*DI, 1);
        // ff2 + bias                 [2048 x 256 x 1024]
        k_gemm_tf32<<<dim3(DM/64, (SEG*BSZ)/128), 256>>>(4, ff_w2 + (size_t)i*DI*DM, 2,
                                                         SEG*BSZ, DM, DI, ff_b2 + i*DM, 0);
        k_addln<<<SEG*BSZ, DM>>>(2, ln2_g + i*DM, ln2_b + i*DM,
                                 memout + (size_t)(i+1)*SEG*BSZ*DM);
    }
    k_dec<<<(SEG*BSZ)/8, 256>>>(W_dec, b_dec, pred);
}